// round 5
// baseline (speedup 1.0000x reference)
#include <cuda_runtime.h>
#include <cuda_bf16.h>

// Fixed shapes
#define M_ROWS   2048
#define N_LAT    8192
#define DIM      256
#define ROWS_CTA 16
#define LATS_CTA 256
#define NRB      (M_ROWS / ROWS_CTA)   // 128
#define NLB      (N_LAT / LATS_CTA)    // 32
#define NQ_TOT   (DIM / 4)             // 64 quads
#define NSTAGE   16                    // stages of 16 floats (4 quads)
#define QPS      4

typedef unsigned long long ull;

__device__ float g_cand[M_ROWS * NLB * 4];
__device__ float g_tail[M_ROWS];

// A += |R + L|  (packed f32x2; R holds negated row values)
#define ABSACC(A, R, L) do { ull _d;                                \
    asm("add.rn.f32x2 %0, %1, %2;" : "=l"(_d) : "l"(R), "l"(L));    \
    _d &= 0x7fffffff7fffffffULL;                                    \
    asm("add.rn.f32x2 %0, %1, %2;" : "=l"(A) : "l"(A), "l"(_d));    \
} while (0)

#define CP16(dst_u32, src_ptr) \
    asm volatile("cp.async.cg.shared.global [%0], [%1], 16;" :: "r"(dst_u32), "l"(src_ptr))
#define CP_COMMIT()  asm volatile("cp.async.commit_group;" ::: "memory")
#define CP_WAIT0()   asm volatile("cp.async.wait_group 0;" ::: "memory")

static __device__ __forceinline__ void ins4(float v, float& m0, float& m1, float& m2, float& m3) {
    if (v < m3) {
        float c2 = fminf(v,  m2), d3 = fmaxf(v,  m2);
        float c1 = fminf(c2, m1), d2 = fmaxf(c2, m1);
        float c0 = fminf(c1, m0), d1 = fmaxf(c1, m0);
        m0 = c0; m1 = d1; m2 = d2; m3 = d3;
    }
}

static __device__ __forceinline__ float huber1(float x) {
    return (x < 1.0f) ? (0.5f * x * x) : (x - 0.5f);
}

// ---------------------------------------------------------------------------
// Kernel 1: L1 cdist over a 16-row x 256-latent tile; min-4 per (row, latblock)
// grid (128, 32), block 256, 3 CTAs/SM
// ---------------------------------------------------------------------------
__global__ void __launch_bounds__(256, 3)
k1_cdist_min4(const float* __restrict__ space, const float* __restrict__ lat) {
    __shared__ float4 rowS[NQ_TOT][ROWS_CTA];   // 16KB persistent (negated rows)
    __shared__ float4 latS[2][QPS][LATS_CTA];   // 32KB double-buffered

    const int tid = threadIdx.x;
    const int rowBase = blockIdx.x * ROWS_CTA;
    const int latBase = blockIdx.y * LATS_CTA;
    const int r0 = (tid >> 6) * 4;     // warp-uniform: 0,4,8,12
    const int c0 = tid & 63;           // lats c0, c0+64, c0+128, c0+192

    // ---- stage rows negated: unit u -> row u&15, quad u>>4 (conflict-free STS) ----
    #pragma unroll
    for (int k = 0; k < 4; ++k) {
        int u = tid + k * 256;
        int r = u & 15, q = u >> 4;
        float4 v = reinterpret_cast<const float4*>(space + (size_t)(rowBase + r) * DIM)[q];
        rowS[q][r] = make_float4(-v.x, -v.y, -v.z, -v.w);
    }

    const float* lsrc = lat + (size_t)(latBase + tid) * DIM;  // thread stages latent `tid`

    {   // prologue: stage 0 -> buf 0
        #pragma unroll
        for (int j = 0; j < QPS; ++j) {
            unsigned d = (unsigned)__cvta_generic_to_shared(&latS[0][j][tid]);
            CP16(d, lsrc + 4 * j);
        }
        CP_COMMIT();
    }

    ull acc[4][4];
    #pragma unroll
    for (int i = 0; i < 4; ++i)
        #pragma unroll
        for (int j = 0; j < 4; ++j) acc[i][j] = 0ULL;

    for (int s = 0; s < NSTAGE; ++s) {
        CP_WAIT0();
        __syncthreads();   // stage-s latents visible; prev buf free; rowS staged (s==0)

        if (s + 1 < NSTAGE) {
            const float* sp = lsrc + (s + 1) * 16;
            #pragma unroll
            for (int j = 0; j < QPS; ++j) {
                unsigned d = (unsigned)__cvta_generic_to_shared(&latS[(s + 1) & 1][j][tid]);
                CP16(d, sp + 4 * j);
            }
            CP_COMMIT();
        }

        #pragma unroll
        for (int q = 0; q < QPS; ++q) {
            const float4* lb = &latS[s & 1][q][0];
            ulonglong2 lv0 = *reinterpret_cast<const ulonglong2*>(lb + c0);
            ulonglong2 lv1 = *reinterpret_cast<const ulonglong2*>(lb + c0 + 64);
            ulonglong2 lv2 = *reinterpret_cast<const ulonglong2*>(lb + c0 + 128);
            ulonglong2 lv3 = *reinterpret_cast<const ulonglong2*>(lb + c0 + 192);
            const float4* rb = &rowS[QPS * s + q][r0];
            #pragma unroll
            for (int ri = 0; ri < 4; ++ri) {
                ulonglong2 rv = *reinterpret_cast<const ulonglong2*>(rb + ri);
                ABSACC(acc[ri][0], rv.x, lv0.x); ABSACC(acc[ri][0], rv.y, lv0.y);
                ABSACC(acc[ri][1], rv.x, lv1.x); ABSACC(acc[ri][1], rv.y, lv1.y);
                ABSACC(acc[ri][2], rv.x, lv2.x); ABSACC(acc[ri][2], rv.y, lv2.y);
                ABSACC(acc[ri][3], rv.x, lv3.x); ABSACC(acc[ri][3], rv.y, lv3.y);
            }
        }
    }

    // ---- epilogue: fold packed halves -> dist matrix in smem ----
    __syncthreads();   // everyone done reading rowS
    float* db = reinterpret_cast<float*>(&rowS[0][0]);   // [16][256] floats
    #pragma unroll
    for (int ri = 0; ri < 4; ++ri) {
        float* drow = db + (r0 + ri) * LATS_CTA;
        #pragma unroll
        for (int j = 0; j < 4; ++j) {
            float lo = __uint_as_float((unsigned)(acc[ri][j] & 0xffffffffULL));
            float hi = __uint_as_float((unsigned)(acc[ri][j] >> 32));
            drow[c0 + 64 * j] = lo + hi;
        }
    }
    __syncthreads();

    // stage-1 reduce: thread -> row tid>>4, 16-float segment (tid&15), staggered
    {
        int row = tid >> 4;
        int seg = (tid & 15) * 16;
        const float* p = db + row * LATS_CTA;
        float m0 = 1e30f, m1 = 1e30f, m2 = 1e30f, m3 = 1e30f;
        #pragma unroll 8
        for (int q = 0; q < 16; ++q)
            ins4(p[seg + ((q + tid) & 15)], m0, m1, m2, m3);
        float4* c4 = reinterpret_cast<float4*>(&latS[0][0][0]);   // [16][16] float4
        c4[row * 16 + (tid & 15)] = make_float4(m0, m1, m2, m3);
    }
    __syncthreads();

    if (tid < ROWS_CTA) {
        const float* cf = reinterpret_cast<const float*>(&latS[0][0][0]) + tid * 64;
        float m0 = 1e30f, m1 = 1e30f, m2 = 1e30f, m3 = 1e30f;
        #pragma unroll 8
        for (int k = 0; k < 64; ++k)
            ins4(cf[(k + 4 * tid) & 63], m0, m1, m2, m3);
        float4* dst = reinterpret_cast<float4*>(
            g_cand + ((size_t)(rowBase + tid) * NLB + blockIdx.y) * 4);
        *dst = make_float4(m0, m1, m2, m3);
    }
}

// ---------------------------------------------------------------------------
__global__ void k2_merge_tail() {
    int idx = blockIdx.x * blockDim.x + threadIdx.x;
    if (idx >= M_ROWS) return;
    const float* p = g_cand + (size_t)idx * NLB * 4;
    float m0 = 1e30f, m1 = 1e30f, m2 = 1e30f, m3 = 1e30f;
    #pragma unroll 4
    for (int q = 0; q < NLB * 4; ++q) ins4(p[q], m0, m1, m2, m3);
    g_tail[idx] = (m0 + m1 + m2 + m3) * 0.25f;
}

// ---------------------------------------------------------------------------
// Kernel 3: top-64 largest of tail[2048] via bit binary search, huber mean
// ---------------------------------------------------------------------------
__global__ void k3_top64_huber(float* __restrict__ out) {
    __shared__ int   wred[8];
    __shared__ float wfred[8];
    __shared__ unsigned s_lo, s_hi;
    const int t = threadIdx.x;

    unsigned b[8];
    #pragma unroll
    for (int k = 0; k < 8; ++k) b[k] = __float_as_uint(g_tail[t + 256 * k]);

    if (t == 0) { s_lo = 0u; s_hi = 0x7f800000u; }
    __syncthreads();
    unsigned lo = s_lo, hi = s_hi;

    while (hi - lo > 1u) {
        unsigned mid = lo + ((hi - lo) >> 1);
        int c = 0;
        #pragma unroll
        for (int k = 0; k < 8; ++k) c += (b[k] >= mid);
        #pragma unroll
        for (int o = 16; o; o >>= 1) c += __shfl_down_sync(0xffffffffu, c, o);
        if ((t & 31) == 0) wred[t >> 5] = c;
        __syncthreads();
        if (t == 0) {
            int tot = 0;
            #pragma unroll
            for (int w = 0; w < 8; ++w) tot += wred[w];
            if (tot >= 64) s_lo = mid; else s_hi = mid;
        }
        __syncthreads();
        lo = s_lo; hi = s_hi;
        __syncthreads();
    }

    int c = 0; float hs = 0.0f;
    #pragma unroll
    for (int k = 0; k < 8; ++k)
        if (b[k] > lo) { ++c; hs += huber1(__uint_as_float(b[k])); }
    #pragma unroll
    for (int o = 16; o; o >>= 1) {
        c  += __shfl_down_sync(0xffffffffu, c, o);
        hs += __shfl_down_sync(0xffffffffu, hs, o);
    }
    if ((t & 31) == 0) { wred[t >> 5] = c; wfred[t >> 5] = hs; }
    __syncthreads();
    if (t == 0) {
        int ngt = 0; float tot = 0.0f;
        #pragma unroll
        for (int w = 0; w < 8; ++w) { ngt += wred[w]; tot += wfred[w]; }
        float tv = __uint_as_float(lo);
        out[0] = (tot + (float)(64 - ngt) * huber1(tv)) * (1.0f / 64.0f);
    }
}

// ---------------------------------------------------------------------------
extern "C" void kernel_launch(void* const* d_in, const int* in_sizes, int n_in,
                              void* d_out, int out_size) {
    const float* a = (const float*)d_in[0];
    const float* b = (const float*)d_in[1];
    const float *space, *lats;
    if (in_sizes[0] == M_ROWS * DIM) { space = a; lats = b; }
    else                             { space = b; lats = a; }

    dim3 g1(NRB, NLB);   // 128 x 32
    k1_cdist_min4<<<g1, 256>>>(space, lats);
    k2_merge_tail<<<(M_ROWS + 255) / 256, 256>>>();
    k3_top64_huber<<<1, 256>>>((float*)d_out);
}

// round 7
// speedup vs baseline: 1.2867x; 1.2867x over previous
#include <cuda_runtime.h>
#include <cuda_bf16.h>

// Fixed shapes
#define M_ROWS   2048
#define N_LAT    8192
#define DIM      256
#define ROWS_CTA 32
#define LATS_CTA 256
#define NRB      (M_ROWS / ROWS_CTA)   // 64
#define NLB      (N_LAT / LATS_CTA)    // 32
#define NQ_TOT   (DIM / 4)             // 64 quads
#define NSTAGE   16                    // stages of 16 floats (4 quads)
#define QPS      4
#define STAGE_BYTES (QPS * LATS_CTA * 16)   // 16KB

typedef unsigned long long ull;

__device__ float4 g_latT[NQ_TOT * N_LAT];   // quad-major transposed latents (8MB)
__device__ float  g_cand[M_ROWS * NLB * 4];
__device__ float  g_tail[M_ROWS];

// A += |R + L|  (packed f32x2; R holds negated row values)
#define ABSACC(A, R, L) do { ull _d;                                \
    asm("add.rn.f32x2 %0, %1, %2;" : "=l"(_d) : "l"(R), "l"(L));    \
    _d &= 0x7fffffff7fffffffULL;                                    \
    asm("add.rn.f32x2 %0, %1, %2;" : "=l"(A) : "l"(A), "l"(_d));    \
} while (0)

#define MBAR_INIT(a, c) \
    asm volatile("mbarrier.init.shared.b64 [%0], %1;" :: "r"(a), "r"(c) : "memory")
#define MBAR_EXPECT(a, b) \
    asm volatile("mbarrier.arrive.expect_tx.shared.b64 _, [%0], %1;" :: "r"(a), "r"(b) : "memory")
#define BULK_G2S(dst, src, n, bar) \
    asm volatile("cp.async.bulk.shared::cluster.global.mbarrier::complete_tx::bytes [%0], [%1], %2, [%3];" \
                 :: "r"(dst), "l"(src), "r"(n), "r"(bar) : "memory")

static __device__ __forceinline__ void mbar_wait(unsigned bar, unsigned parity) {
    asm volatile(
        "{\n\t"
        ".reg .pred P;\n\t"
        "WAIT_%=:\n\t"
        "mbarrier.try_wait.parity.acquire.cta.shared::cta.b64 P, [%0], %1, 0x989680;\n\t"
        "@P bra.uni DONE_%=;\n\t"
        "bra.uni WAIT_%=;\n\t"
        "DONE_%=:\n\t"
        "}" :: "r"(bar), "r"(parity) : "memory");
}

static __device__ __forceinline__ void ins4(float v, float& m0, float& m1, float& m2, float& m3) {
    if (v < m3) {
        float c2 = fminf(v,  m2), d3 = fmaxf(v,  m2);
        float c1 = fminf(c2, m1), d2 = fmaxf(c2, m1);
        float c0 = fminf(c1, m0), d1 = fmaxf(c1, m0);
        m0 = c0; m1 = d1; m2 = d2; m3 = d3;
    }
}

static __device__ __forceinline__ float huber1(float x) {
    return (x < 1.0f) ? (0.5f * x * x) : (x - 0.5f);
}

// ---------------------------------------------------------------------------
// Kernel 0: transpose latents -> g_latT[quad][lat] (float4 of 4 consecutive d)
// grid 256, block 256: each block handles 32 latent rows
// ---------------------------------------------------------------------------
__global__ void k0_transpose(const float* __restrict__ lat) {
    __shared__ float4 sm[32][65];   // padded
    const int tid = threadIdx.x;
    const int lb = blockIdx.x * 32;
    #pragma unroll
    for (int k = 0; k < 8; ++k) {
        int idx = tid + k * 256;      // 2048 float4
        int r = idx >> 6, q = idx & 63;
        sm[r][q] = reinterpret_cast<const float4*>(lat)[(size_t)(lb + r) * 64 + q];
    }
    __syncthreads();
    #pragma unroll
    for (int k = 0; k < 8; ++k) {
        int idx = tid + k * 256;
        int q = idx >> 5, l = idx & 31;
        g_latT[(size_t)q * N_LAT + lb + l] = sm[l][q];
    }
}

// ---------------------------------------------------------------------------
// Kernel 1: L1 cdist 32-row x 256-latent tile; min-4 per (row, latblock)
// grid (64, 32), block 256, 2 CTAs/SM. Latents staged via cp.async.bulk.
// ---------------------------------------------------------------------------
__global__ void __launch_bounds__(256, 2)
k1_cdist_min4(const float* __restrict__ space, const float* __restrict__ lat) {
    __shared__ float4 rowS[NQ_TOT][ROWS_CTA];     // 32KB persistent (negated rows)
    __shared__ float4 latS[2][QPS][LATS_CTA];     // 2 x 16KB double-buffered
    __shared__ ull    mbar[2];

    const int tid = threadIdx.x;
    const int rowBase = blockIdx.x * ROWS_CTA;
    const int latBase = blockIdx.y * LATS_CTA;
    const int r0 = (tid >> 6) * 8;     // warp-uniform: 0,8,16,24
    const int c0 = tid & 63;           // lats c0, c0+64, c0+128, c0+192

    const unsigned bar0 = (unsigned)__cvta_generic_to_shared(&mbar[0]);
    const unsigned bar1 = (unsigned)__cvta_generic_to_shared(&mbar[1]);

    if (tid == 0) { MBAR_INIT(bar0, 1); MBAR_INIT(bar1, 1); }

    // ---- stage rows negated: unit u -> row u&31, quad u>>5 (conflict-free) ----
    #pragma unroll
    for (int k = 0; k < 8; ++k) {
        int u = tid + k * 256;
        int r = u & 31, q = u >> 5;
        float4 v = reinterpret_cast<const float4*>(space + (size_t)(rowBase + r) * DIM)[q];
        rowS[q][r] = make_float4(-v.x, -v.y, -v.z, -v.w);
    }
    __syncthreads();   // mbar init + rowS visible

    // prologue: stage 0 -> buf 0
    if (tid == 0) {
        MBAR_EXPECT(bar0, STAGE_BYTES);
        unsigned d = (unsigned)__cvta_generic_to_shared(&latS[0][0][0]);
        #pragma unroll
        for (int j = 0; j < QPS; ++j)
            BULK_G2S(d + j * LATS_CTA * 16,
                     (const char*)(g_latT + (size_t)j * N_LAT + latBase),
                     LATS_CTA * 16, bar0);
    }

    ull acc[8][4];
    #pragma unroll
    for (int i = 0; i < 8; ++i)
        #pragma unroll
        for (int j = 0; j < 4; ++j) acc[i][j] = 0ULL;

    for (int s = 0; s < NSTAGE; ++s) {
        mbar_wait((s & 1) ? bar1 : bar0, (s >> 1) & 1);
        __syncthreads();   // all threads passed wait => done reading buf[(s+1)&1]

        if (s + 1 < NSTAGE && tid == 0) {
            unsigned nb = ((s + 1) & 1) ? bar1 : bar0;
            MBAR_EXPECT(nb, STAGE_BYTES);
            unsigned d = (unsigned)__cvta_generic_to_shared(&latS[(s + 1) & 1][0][0]);
            #pragma unroll
            for (int j = 0; j < QPS; ++j)
                BULK_G2S(d + j * LATS_CTA * 16,
                         (const char*)(g_latT + (size_t)(QPS * (s + 1) + j) * N_LAT + latBase),
                         LATS_CTA * 16, nb);
        }

        #pragma unroll
        for (int q = 0; q < QPS; ++q) {
            const float4* lb = &latS[s & 1][q][0];
            ulonglong2 lv0 = *reinterpret_cast<const ulonglong2*>(lb + c0);
            ulonglong2 lv1 = *reinterpret_cast<const ulonglong2*>(lb + c0 + 64);
            ulonglong2 lv2 = *reinterpret_cast<const ulonglong2*>(lb + c0 + 128);
            ulonglong2 lv3 = *reinterpret_cast<const ulonglong2*>(lb + c0 + 192);
            const float4* rb = &rowS[QPS * s + q][r0];
            #pragma unroll
            for (int ri = 0; ri < 8; ++ri) {
                ulonglong2 rv = *reinterpret_cast<const ulonglong2*>(rb + ri);
                ABSACC(acc[ri][0], rv.x, lv0.x); ABSACC(acc[ri][0], rv.y, lv0.y);
                ABSACC(acc[ri][1], rv.x, lv1.x); ABSACC(acc[ri][1], rv.y, lv1.y);
                ABSACC(acc[ri][2], rv.x, lv2.x); ABSACC(acc[ri][2], rv.y, lv2.y);
                ABSACC(acc[ri][3], rv.x, lv3.x); ABSACC(acc[ri][3], rv.y, lv3.y);
            }
        }
    }

    // ---- epilogue: fold packed halves -> dist matrix in smem ----
    __syncthreads();   // everyone done reading rowS
    float* db = reinterpret_cast<float*>(&rowS[0][0]);   // [32][256] floats
    #pragma unroll
    for (int ri = 0; ri < 8; ++ri) {
        float* drow = db + (r0 + ri) * LATS_CTA;
        #pragma unroll
        for (int j = 0; j < 4; ++j) {
            float lo = __uint_as_float((unsigned)(acc[ri][j] & 0xffffffffULL));
            float hi = __uint_as_float((unsigned)(acc[ri][j] >> 32));
            drow[c0 + 64 * j] = lo + hi;
        }
    }
    __syncthreads();

    // stage-1 reduce: thread -> row tid>>3, 32-float segment (tid&7), staggered
    {
        int row = tid >> 3;
        int seg = (tid & 7) * 32;
        const float* p = db + row * LATS_CTA;
        float m0 = 1e30f, m1 = 1e30f, m2 = 1e30f, m3 = 1e30f;
        #pragma unroll 8
        for (int q = 0; q < 32; ++q)
            ins4(p[seg + ((q + tid) & 31)], m0, m1, m2, m3);
        float4* c4 = reinterpret_cast<float4*>(&latS[0][0][0]);   // [32][8] float4
        c4[row * 8 + (tid & 7)] = make_float4(m0, m1, m2, m3);
    }
    __syncthreads();

    if (tid < ROWS_CTA) {
        const float* cf = reinterpret_cast<const float*>(&latS[0][0][0]) + tid * 32;
        float m0 = 1e30f, m1 = 1e30f, m2 = 1e30f, m3 = 1e30f;
        #pragma unroll 8
        for (int k = 0; k < 32; ++k)
            ins4(cf[(k + tid) & 31], m0, m1, m2, m3);
        float4* dst = reinterpret_cast<float4*>(
            g_cand + ((size_t)(rowBase + tid) * NLB + blockIdx.y) * 4);
        *dst = make_float4(m0, m1, m2, m3);
    }
}

// ---------------------------------------------------------------------------
__global__ void k2_merge_tail() {
    int idx = blockIdx.x * blockDim.x + threadIdx.x;
    if (idx >= M_ROWS) return;
    const float* p = g_cand + (size_t)idx * NLB * 4;
    float m0 = 1e30f, m1 = 1e30f, m2 = 1e30f, m3 = 1e30f;
    #pragma unroll 4
    for (int q = 0; q < NLB * 4; ++q) ins4(p[q], m0, m1, m2, m3);
    g_tail[idx] = (m0 + m1 + m2 + m3) * 0.25f;
}

// ---------------------------------------------------------------------------
// Kernel 3: top-64 largest of tail[2048] via bit binary search, huber mean
// ---------------------------------------------------------------------------
__global__ void k3_top64_huber(float* __restrict__ out) {
    __shared__ int   wred[8];
    __shared__ float wfred[8];
    __shared__ unsigned s_lo, s_hi;
    const int t = threadIdx.x;

    unsigned b[8];
    #pragma unroll
    for (int k = 0; k < 8; ++k) b[k] = __float_as_uint(g_tail[t + 256 * k]);

    if (t == 0) { s_lo = 0u; s_hi = 0x7f800000u; }
    __syncthreads();
    unsigned lo = s_lo, hi = s_hi;

    while (hi - lo > 1u) {
        unsigned mid = lo + ((hi - lo) >> 1);
        int c = 0;
        #pragma unroll
        for (int k = 0; k < 8; ++k) c += (b[k] >= mid);
        #pragma unroll
        for (int o = 16; o; o >>= 1) c += __shfl_down_sync(0xffffffffu, c, o);
        if ((t & 31) == 0) wred[t >> 5] = c;
        __syncthreads();
        if (t == 0) {
            int tot = 0;
            #pragma unroll
            for (int w = 0; w < 8; ++w) tot += wred[w];
            if (tot >= 64) s_lo = mid; else s_hi = mid;
        }
        __syncthreads();
        lo = s_lo; hi = s_hi;
        __syncthreads();
    }

    int c = 0; float hs = 0.0f;
    #pragma unroll
    for (int k = 0; k < 8; ++k)
        if (b[k] > lo) { ++c; hs += huber1(__uint_as_float(b[k])); }
    #pragma unroll
    for (int o = 16; o; o >>= 1) {
        c  += __shfl_down_sync(0xffffffffu, c, o);
        hs += __shfl_down_sync(0xffffffffu, hs, o);
    }
    if ((t & 31) == 0) { wred[t >> 5] = c; wfred[t >> 5] = hs; }
    __syncthreads();
    if (t == 0) {
        int ngt = 0; float tot = 0.0f;
        #pragma unroll
        for (int w = 0; w < 8; ++w) { ngt += wred[w]; tot += wfred[w]; }
        float tv = __uint_as_float(lo);
        out[0] = (tot + (float)(64 - ngt) * huber1(tv)) * (1.0f / 64.0f);
    }
}

// ---------------------------------------------------------------------------
extern "C" void kernel_launch(void* const* d_in, const int* in_sizes, int n_in,
                              void* d_out, int out_size) {
    const float* a = (const float*)d_in[0];
    const float* b = (const float*)d_in[1];
    const float *space, *lats;
    if (in_sizes[0] == M_ROWS * DIM) { space = a; lats = b; }
    else                             { space = b; lats = a; }

    k0_transpose<<<N_LAT / 32, 256>>>(lats);
    dim3 g1(NRB, NLB);   // 64 x 32
    k1_cdist_min4<<<g1, 256>>>(space, lats);
    k2_merge_tail<<<(M_ROWS + 255) / 256, 256>>>();
    k3_top64_huber<<<1, 256>>>((float*)d_out);
}